// round 16
// baseline (speedup 1.0000x reference)
#include <cuda_runtime.h>
#include <cuda_bf16.h>
#include <cstdint>

#define TLEN  512
#define FDIM  1024
#define NW    8             // warps per block = time chunks
#define CHUNK (TLEN / NW)   // 64 timesteps per warp
#define NPAIR (CHUNK / 2)   // 32 (t,t+1) pairs per warp
#define SPAIR 12            // pairs staged in smem; rest re-read (L1/L2-hot)

typedef unsigned long long ull;

__device__ __forceinline__ float fast_sqrt(float a) {
    float r; asm("sqrt.approx.f32 %0, %1;" : "=f"(r) : "f"(a)); return r;
}
__device__ __forceinline__ float fast_tanh(float a) {
    float r; asm("tanh.approx.f32 %0, %1;" : "=f"(r) : "f"(a)); return r;
}
// ---- packed f32x2 (sm_100+) ----
__device__ __forceinline__ ull pack2(float lo, float hi) {
    ull r; asm("mov.b64 %0, {%1, %2};" : "=l"(r) : "f"(lo), "f"(hi)); return r;
}
__device__ __forceinline__ void unpack2(ull v, float& lo, float& hi) {
    asm("mov.b64 {%0, %1}, %2;" : "=f"(lo), "=f"(hi) : "l"(v));
}
__device__ __forceinline__ ull add2(ull a, ull b) {
    ull r; asm("add.rn.f32x2 %0, %1, %2;" : "=l"(r) : "l"(a), "l"(b)); return r;
}
__device__ __forceinline__ ull sub2(ull a, ull b) {
    ull r; asm("sub.rn.f32x2 %0, %1, %2;" : "=l"(r) : "l"(a), "l"(b)); return r;
}
__device__ __forceinline__ ull mul2(ull a, ull b) {
    ull r; asm("mul.rn.f32x2 %0, %1, %2;" : "=l"(r) : "l"(a), "l"(b)); return r;
}
__device__ __forceinline__ ull fma2(ull a, ull b, ull c) {
    ull r; asm("fma.rn.f32x2 %0, %1, %2, %3;" : "=l"(r) : "l"(a), "l"(b), "l"(c)); return r;
}

__global__ __launch_bounds__(NW * 32, 6)
void dyn_dense_kernel(const float* __restrict__ x, const float* __restrict__ ws,
                      const float* __restrict__ qs, const float* __restrict__ bias,
                      float* __restrict__ out)
{
    __shared__ float2 sx2[NW][SPAIR][32];          // 24 KB: steps 0..23 as (t,t+1) pairs
    __shared__ float2 invc2[TLEN / 2];             //  2 KB: (1/(2p+1), 1/(2p+2))
    __shared__ float  sm_s[NW][32];                //  3 KB partials
    __shared__ float  sm_m[NW][32];
    __shared__ float  sm_q[NW][32];
    // total static smem ~29.6 KB -> 6 blocks/SM = 178 KB, ~50 KB left for L1D

    const int tid  = threadIdx.x;
    const int warp = tid >> 5;
    const int lane = tid & 31;

    // 256 threads, 256 pair-entries: one each
    invc2[tid] = make_float2(1.0f / (float)(2 * tid + 1),
                             1.0f / (float)(2 * tid + 2));

    // grid = B * (FDIM/32); block covers 32 consecutive f, all of T
    const int fblk = blockIdx.x & (FDIM / 32 - 1);
    const int b    = blockIdx.x >> 5;
    const int f    = fblk * 32 + lane;

    const size_t colbase = (size_t)b * TLEN * FDIM + (size_t)(warp * CHUNK) * FDIM + f;
    const float* p = x + colbase;

    // ---- Phase 1: load chunk ONCE (4 batches of 16); stage steps < 2*SPAIR to smem,
    //      accumulate partials over all 64. Max identity 0.0f = Keras zero-init. ----
    float ps = 0.0f, pm = 0.0f, pq = 0.0f;
    #pragma unroll
    for (int t0 = 0; t0 < CHUNK; t0 += 16) {
        float xv[16];
        #pragma unroll
        for (int u = 0; u < 16; u++)
            xv[u] = __ldg(p + (t0 + u) * FDIM);    // 16 LDGs in flight
        #pragma unroll
        for (int u = 0; u < 16; u += 2) {
            const int t = t0 + u;                  // compile-time
            if (t < 2 * SPAIR)
                sx2[warp][t >> 1][lane] = make_float2(xv[u], xv[u + 1]);  // STS.64
            ps += xv[u];  ps += xv[u + 1];
            pq  = fmaf(xv[u], xv[u], pq);
            pq  = fmaf(xv[u + 1], xv[u + 1], pq);
            pm  = fmaxf(pm, xv[u]);
            pm  = fmaxf(pm, xv[u + 1]);
        }
    }
    if (warp < NW - 1) {                           // last warp's partials feed nobody
        sm_s[warp][lane] = ps;
        sm_m[warp][lane] = pm;
        sm_q[warp][lane] = pq;
    }
    __syncthreads();

    // ---- Phase 2: exclusive prefix over earlier chunks ----
    float s = 0.0f, m = 0.0f, ss = 0.0f;
    #pragma unroll
    for (int w = 0; w < NW - 1; w++) {
        if (w < warp) {
            s  += sm_s[w][lane];
            m   = fmaxf(m, sm_m[w][lane]);
            ss += sm_q[w][lane];
        }
    }

    // per-aggregation weights (AGGS = sum,max,mean,var,std), duplicated packed
    const float w0 = __ldg(ws + 0 * FDIM + f);
    const float w1 = __ldg(ws + 1 * FDIM + f);
    const float w2 = __ldg(ws + 2 * FDIM + f);
    const float w3 = __ldg(ws + 3 * FDIM + f);
    const float w4 = __ldg(ws + 4 * FDIM + f);
    const float q0 = __ldg(qs + 0 * FDIM + f);
    const float q1 = __ldg(qs + 1 * FDIM + f);
    // fold exact eps-correction into bias (z-chain uses w3*(var+eps))
    const float bz = fmaf(-w3, 1e-4f, __ldg(bias + f));

    const ull W0P = pack2(w0, w0);
    const ull W1P = pack2(w1, w1);
    const ull W2P = pack2(w2, w2);
    const ull W3P = pack2(w3, w3);
    const ull W4P = pack2(w4, w4);
    const ull Q0P = pack2(q0, q0);
    const ull Q1P = pack2(q1, q1);
    const ull BZP = pack2(bz, bz);
    const ull EPSP = pack2(1e-4f, 1e-4f);
    const ull TWOP = pack2(2.0f, 2.0f);

    const float c0 = (float)(warp * CHUNK);
    ull CPP = pack2(c0 + 1.0f, c0 + 2.0f);         // counts of the (t, t+1) pair

    float* o = out + colbase;
    const float2* icp = &invc2[warp * NPAIR];

    // one packed pair-step: serial state twice (exact), then packed z-chain
    auto pairstep = [&](float2 xp2, int sp) {
        const float s1  = s  + xp2.x;              // state after t
        const float ss1 = fmaf(xp2.x, xp2.x, ss);
        const float m1  = fmaxf(m, xp2.x);
        s  = s1 + xp2.y;                           // state after t+1
        ss = fmaf(xp2.y, xp2.y, ss1);
        m  = fmaxf(m1, xp2.y);

        const ull SP  = pack2(s1, s);
        const ull MP  = pack2(m1, m);
        const ull SSP = pack2(ss1, ss);
        const ull ICP = *(const ull*)&icp[sp];     // LDS.64 broadcast (1/c_t, 1/c_{t+1})

        const ull MEANP = mul2(SP, ICP);
        const ull T1P   = fma2(SSP, ICP, EPSP);    // ss/c + eps
        const ull VEPSP = sub2(T1P, mul2(MEANP, MEANP)); // var + eps

        float v0, v1; unpack2(VEPSP, v0, v1);
        const ull SDP = pack2(fast_sqrt(v0), fast_sqrt(v1));

        ull ZP = fma2(Q1P, CPP, Q0P);              // count polynomial
        ZP = fma2(ZP, CPP, BZP);                   // BZP holds eps fix
        ZP = fma2(W0P, SP,    ZP);
        ZP = fma2(W1P, MP,    ZP);
        ZP = fma2(W2P, MEANP, ZP);
        ZP = fma2(W3P, VEPSP, ZP);
        ZP = fma2(W4P, SDP,   ZP);
        CPP = add2(CPP, TWOP);

        float z0, z1; unpack2(ZP, z0, z1);
        // streaming stores: out is write-once; keep x resident in L1/L2
        __stcs(o + (2 * sp)     * FDIM, fast_tanh(z0));
        __stcs(o + (2 * sp + 1) * FDIM, fast_tanh(z1));
    };

    // prefetch first TWO re-read pairs (steps 24..27) — L1/L2-hot from phase 1
    const float* pr = p + 2 * SPAIR * FDIM;
    float2 nxt0 = make_float2(__ldg(pr),            __ldg(pr + FDIM));
    float2 nxt1 = make_float2(__ldg(pr + 2 * FDIM), __ldg(pr + 3 * FDIM));

    // pairs 0..SPAIR-1 from smem (LDS.64)
    #pragma unroll
    for (int sp = 0; sp < SPAIR; sp++)
        pairstep(sx2[warp][sp][lane], sp);

    // pairs SPAIR..NPAIR-1 re-read from global with depth-2 rolling prefetch
    #pragma unroll
    for (int g = 0; g < NPAIR - SPAIR; g++) {
        const float2 cur = nxt0;
        nxt0 = nxt1;
        if (g < NPAIR - SPAIR - 2) {
            const float* q = pr + 2 * (g + 2) * FDIM;
            nxt1 = make_float2(__ldg(q), __ldg(q + FDIM));
        }
        pairstep(cur, SPAIR + g);
    }
}

extern "C" void kernel_launch(void* const* d_in, const int* in_sizes, int n_in,
                              void* d_out, int out_size)
{
    const float* x    = (const float*)d_in[0];
    const float* ws   = (const float*)d_in[1];
    const float* qs   = (const float*)d_in[2];
    const float* bias = (const float*)d_in[3];
    float* out = (float*)d_out;

    const int grid = 32 * (FDIM / 32);   // B * 32 f-tiles = 1024 blocks
    dyn_dense_kernel<<<grid, NW * 32>>>(x, ws, qs, bias, out);
}

// round 17
// speedup vs baseline: 1.1250x; 1.1250x over previous
#include <cuda_runtime.h>
#include <cuda_bf16.h>
#include <cstdint>

#define TLEN  512
#define FDIM  1024
#define NW    16            // warps per block = time chunks
#define CHUNK (TLEN / NW)   // 32 timesteps per warp
#define NPAIR (CHUNK / 2)   // 16 (t,t+1) pairs per warp
#define SPAIR 8             // pairs staged in smem; rest re-read (L1/L2-hot)

typedef unsigned long long ull;

__device__ __forceinline__ float fast_sqrt(float a) {
    float r; asm("sqrt.approx.f32 %0, %1;" : "=f"(r) : "f"(a)); return r;
}
__device__ __forceinline__ float fast_tanh(float a) {
    float r; asm("tanh.approx.f32 %0, %1;" : "=f"(r) : "f"(a)); return r;
}
// ---- packed f32x2 (sm_100+) ----
__device__ __forceinline__ ull pack2(float lo, float hi) {
    ull r; asm("mov.b64 %0, {%1, %2};" : "=l"(r) : "f"(lo), "f"(hi)); return r;
}
__device__ __forceinline__ void unpack2(ull v, float& lo, float& hi) {
    asm("mov.b64 {%0, %1}, %2;" : "=f"(lo), "=f"(hi) : "l"(v));
}
__device__ __forceinline__ ull add2(ull a, ull b) {
    ull r; asm("add.rn.f32x2 %0, %1, %2;" : "=l"(r) : "l"(a), "l"(b)); return r;
}
__device__ __forceinline__ ull sub2(ull a, ull b) {
    ull r; asm("sub.rn.f32x2 %0, %1, %2;" : "=l"(r) : "l"(a), "l"(b)); return r;
}
__device__ __forceinline__ ull mul2(ull a, ull b) {
    ull r; asm("mul.rn.f32x2 %0, %1, %2;" : "=l"(r) : "l"(a), "l"(b)); return r;
}
__device__ __forceinline__ ull fma2(ull a, ull b, ull c) {
    ull r; asm("fma.rn.f32x2 %0, %1, %2, %3;" : "=l"(r) : "l"(a), "l"(b), "l"(c)); return r;
}

__global__ __launch_bounds__(NW * 32, 3)
void dyn_dense_kernel(const float* __restrict__ x, const float* __restrict__ ws,
                      const float* __restrict__ qs, const float* __restrict__ bias,
                      float* __restrict__ out)
{
    __shared__ float2 sx2[NW][SPAIR][32];          // 32 KB: first 16 steps as (t,t+1) pairs
    __shared__ float2 invc2[TLEN / 2];             //  2 KB: (1/(2p+1), 1/(2p+2))
    __shared__ float  sm_s[NW][32];                //  6 KB partials
    __shared__ float  sm_m[NW][32];
    __shared__ float  sm_q[NW][32];
    // total static smem: 40 KB (no dynamic smem path)

    const int tid  = threadIdx.x;
    const int warp = tid >> 5;
    const int lane = tid & 31;

    if (tid < TLEN / 2)
        invc2[tid] = make_float2(1.0f / (float)(2 * tid + 1),
                                 1.0f / (float)(2 * tid + 2));

    // grid = B * (FDIM/32); block covers 32 consecutive f, all of T
    const int fblk = blockIdx.x & (FDIM / 32 - 1);
    const int b    = blockIdx.x >> 5;
    const int f    = fblk * 32 + lane;

    const size_t colbase = (size_t)b * TLEN * FDIM + (size_t)(warp * CHUNK) * FDIM + f;
    const float* p = x + colbase;

    // ---- Phase 1: load chunk ONCE; stage first 16 steps to smem as pairs.
    //      Packed even/odd accumulators for sum & sumsq; scalar chain for max.
    //      Max identity 0.0f = Keras zero-init. ----
    ull PS2 = pack2(0.0f, 0.0f);
    ull PQ2 = pack2(0.0f, 0.0f);
    float pm = 0.0f;
    {
        float xv[16];
        #pragma unroll
        for (int u = 0; u < 16; u++)
            xv[u] = __ldg(p + u * FDIM);           // 16 LDGs in flight
        #pragma unroll
        for (int u = 0; u < 16; u += 2) {
            sx2[warp][u >> 1][lane] = make_float2(xv[u], xv[u + 1]);  // STS.64
            const ull XP = pack2(xv[u], xv[u + 1]);
            PS2 = add2(PS2, XP);
            PQ2 = fma2(XP, XP, PQ2);
            pm  = fmaxf(fmaxf(pm, xv[u]), xv[u + 1]);
        }
    }
    {
        float xw[16];
        #pragma unroll
        for (int u = 0; u < 16; u++)
            xw[u] = __ldg(p + (16 + u) * FDIM);
        #pragma unroll
        for (int u = 0; u < 16; u += 2) {
            const ull XP = pack2(xw[u], xw[u + 1]);
            PS2 = add2(PS2, XP);
            PQ2 = fma2(XP, XP, PQ2);
            pm  = fmaxf(fmaxf(pm, xw[u]), xw[u + 1]);
        }
    }   // xw dead; its lines stay L1/L2-resident for the phase-2 re-read
    if (warp < NW - 1) {                           // last warp's partials feed nobody
        float a0, a1;
        unpack2(PS2, a0, a1); sm_s[warp][lane] = a0 + a1;
        unpack2(PQ2, a0, a1); sm_q[warp][lane] = a0 + a1;
        sm_m[warp][lane] = pm;
    }
    __syncthreads();

    // ---- Phase 2: exclusive prefix over earlier chunks ----
    float s = 0.0f, m = 0.0f, ss = 0.0f;
    #pragma unroll
    for (int w = 0; w < NW - 1; w++) {
        if (w < warp) {
            s  += sm_s[w][lane];
            m   = fmaxf(m, sm_m[w][lane]);
            ss += sm_q[w][lane];
        }
    }

    // per-aggregation weights (AGGS = sum,max,mean,var,std), duplicated packed
    const float w0 = __ldg(ws + 0 * FDIM + f);
    const float w1 = __ldg(ws + 1 * FDIM + f);
    const float w2 = __ldg(ws + 2 * FDIM + f);
    const float w3 = __ldg(ws + 3 * FDIM + f);
    const float w4 = __ldg(ws + 4 * FDIM + f);
    const float q0 = __ldg(qs + 0 * FDIM + f);
    const float q1 = __ldg(qs + 1 * FDIM + f);
    // fold exact eps-correction into bias (z-chain uses w3*(var+eps))
    const float bz = fmaf(-w3, 1e-4f, __ldg(bias + f));

    const ull W0P = pack2(w0, w0);
    const ull W1P = pack2(w1, w1);
    const ull W2P = pack2(w2, w2);
    const ull W3P = pack2(w3, w3);
    const ull W4P = pack2(w4, w4);
    const ull Q0P = pack2(q0, q0);
    const ull Q1P = pack2(q1, q1);
    const ull BZP = pack2(bz, bz);
    const ull EPSP = pack2(1e-4f, 1e-4f);
    const ull TWOP = pack2(2.0f, 2.0f);

    const float c0 = (float)(warp * CHUNK);
    ull CPP = pack2(c0 + 1.0f, c0 + 2.0f);         // counts of the (t, t+1) pair

    float* o = out + colbase;
    const float2* icp = &invc2[warp * NPAIR];

    // one packed pair-step: serial state twice (exact), then packed z-chain
    auto pairstep = [&](float2 xp2, int sp) {
        const float s1  = s  + xp2.x;              // state after t
        const float ss1 = fmaf(xp2.x, xp2.x, ss);
        const float m1  = fmaxf(m, xp2.x);
        s  = s1 + xp2.y;                           // state after t+1
        ss = fmaf(xp2.y, xp2.y, ss1);
        m  = fmaxf(m1, xp2.y);

        const ull SP  = pack2(s1, s);
        const ull MP  = pack2(m1, m);
        const ull SSP = pack2(ss1, ss);
        const ull ICP = *(const ull*)&icp[sp];     // LDS.64 broadcast (1/c_t, 1/c_{t+1})

        const ull MEANP = mul2(SP, ICP);
        const ull T1P   = fma2(SSP, ICP, EPSP);    // ss/c + eps
        const ull VEPSP = sub2(T1P, mul2(MEANP, MEANP)); // var + eps

        float v0, v1; unpack2(VEPSP, v0, v1);
        const ull SDP = pack2(fast_sqrt(v0), fast_sqrt(v1));

        ull ZP = fma2(Q1P, CPP, Q0P);              // count polynomial
        ZP = fma2(ZP, CPP, BZP);                   // BZP holds eps fix
        ZP = fma2(W0P, SP,    ZP);
        ZP = fma2(W1P, MP,    ZP);
        ZP = fma2(W2P, MEANP, ZP);
        ZP = fma2(W3P, VEPSP, ZP);
        ZP = fma2(W4P, SDP,   ZP);
        CPP = add2(CPP, TWOP);

        float z0, z1; unpack2(ZP, z0, z1);
        // streaming stores: out is write-once; keep x resident in L1/L2
        __stcs(o + (2 * sp)     * FDIM, fast_tanh(z0));
        __stcs(o + (2 * sp + 1) * FDIM, fast_tanh(z1));
    };

    // prefetch first TWO re-read pairs (steps 16..19) — L1/L2-hot from phase 1
    const float* pr = p + 16 * FDIM;
    float2 nxt0 = make_float2(__ldg(pr),            __ldg(pr + FDIM));
    float2 nxt1 = make_float2(__ldg(pr + 2 * FDIM), __ldg(pr + 3 * FDIM));

    // pairs 0..7 from smem (LDS.64)
    #pragma unroll
    for (int sp = 0; sp < SPAIR; sp++)
        pairstep(sx2[warp][sp][lane], sp);

    // pairs 8..15 re-read from global with depth-2 rolling prefetch
    #pragma unroll
    for (int g = 0; g < NPAIR - SPAIR; g++) {
        const float2 cur = nxt0;
        nxt0 = nxt1;
        if (g < NPAIR - SPAIR - 2) {
            const float* q = pr + 2 * (g + 2) * FDIM;
            nxt1 = make_float2(__ldg(q), __ldg(q + FDIM));
        }
        pairstep(cur, SPAIR + g);
    }
}

extern "C" void kernel_launch(void* const* d_in, const int* in_sizes, int n_in,
                              void* d_out, int out_size)
{
    const float* x    = (const float*)d_in[0];
    const float* ws   = (const float*)d_in[1];
    const float* qs   = (const float*)d_in[2];
    const float* bias = (const float*)d_in[3];
    float* out = (float*)d_out;

    const int grid = 32 * (FDIM / 32);   // B * 32 f-tiles = 1024 blocks
    dyn_dense_kernel<<<grid, NW * 32>>>(x, ws, qs, bias, out);
}